// round 15
// baseline (speedup 1.0000x reference)
#include <cuda_runtime.h>
#include <cstdint>

#define N_DIS   20000
#define N_MIC   80000
#define N_NODES 100000
#define N_EDGES 1600000
#define F 64
#define SLOPE 0.2f
#define KC 32

#define NB_D ((N_DIS + 127) / 128)   // 157
#define NB_M ((N_MIC + 127) / 128)   // 625
#define NCH_D ((383 + KC - 1) / KC)  // 12
#define NCH_M ((495 + KC - 1) / KC)  // 16

typedef unsigned long long ull;

// ---- scratch (static device globals: allocation-free) ----
__device__ float    g_z[(size_t)N_NODES * F];   // projected features
__device__ float    g_e[N_EDGES];               // edge scores (leaky_relu)
__device__ unsigned g_mkey[N_NODES];            // order-preserving float keys for max
__device__ float    g_den[N_NODES];             // softmax denom -> reciprocal
__device__ float    g_h[(size_t)N_NODES * F];   // accumulated (unnormalized) output
// pre-interleaved W image: per chunk, [kpair 0..15][f 0..63] ull = (W[2k][f], W[2k+1][f])
__device__ ull      g_Wint[(NCH_D + NCH_M) * 1024];

// ---- packed f32x2 helpers ----
__device__ __forceinline__ ull pk2(float a, float b) {
    ull r;
    asm("mov.b64 %0, {%1, %2};" : "=l"(r) : "f"(a), "f"(b));
    return r;
}
__device__ __forceinline__ void upk2(ull v, float& a, float& b) {
    asm("mov.b64 {%0, %1}, %2;" : "=f"(a), "=f"(b) : "l"(v));
}
__device__ __forceinline__ void ffma2(ull& d, ull a, ull b) {
    asm("fma.rn.f32x2 %0, %1, %2, %0;" : "+l"(d) : "l"(a), "l"(b));
}
__device__ __forceinline__ uint32_t smem_u32(const void* p) {
    uint32_t a;
    asm("{ .reg .u64 t; cvta.to.shared.u64 t, %1; cvt.u32.u64 %0, t; }" : "=r"(a) : "l"(p));
    return a;
}

// ============================================================
// init split so gemm_kernel is launch #4 (the profiled slot).
// ============================================================
__global__ void initA_kernel() {
    int i = blockIdx.x * blockDim.x + threadIdx.x;
    if (i < N_NODES * F / 2) g_h[i] = 0.f;
}
__global__ void initB_kernel() {
    int i = blockIdx.x * blockDim.x + threadIdx.x;
    if (i < N_NODES * F / 2) g_h[N_NODES * F / 2 + i] = 0.f;
}
__global__ void prepWM_kernel(const float* __restrict__ Wd, const float* __restrict__ Wm) {
    int i = blockIdx.x * blockDim.x + threadIdx.x;
    if (i < N_NODES) { g_mkey[i] = 0u; g_den[i] = 0.f; }
    if (i < (NCH_D + NCH_M) * 1024) {
        int c = i >> 10;
        int within = i & 1023;
        int kp = within >> 6;
        int f = within & 63;
        const float* W;
        int K, cl;
        if (c < NCH_D) { W = Wd; K = 383; cl = c; }
        else           { W = Wm; K = 495; cl = c - NCH_D; }
        int k0 = cl * KC + 2 * kp;
        float v0 = (k0     < K) ? W[(size_t)k0 * 64 + f]       : 0.f;
        float v1 = (k0 + 1 < K) ? W[(size_t)(k0 + 1) * 64 + f] : 0.f;
        g_Wint[i] = pk2(v0, v1);
    }
}

// ============================================================
// MERGED GEMM: 128-row tiles, 512 threads, 4 rows x 4 features/thread.
// k-parity FFMA2, cp.async staging, conflict-free permuted W layout
// (slot t<16: features {4t,4t+1}; t>=16: {4(t-16)+2, 4(t-16)+3}).
// 32 regs of accumulator -> target <=64 regs -> 2 blocks (32 warps)/SM.
// ============================================================
#define XSF_STRIDE       36
#define XS_BYTES_PER_BUF (128 * XSF_STRIDE * 4)          // 18432
#define WS_BYTE_BASE     (2 * XS_BYTES_PER_BUF)          // 36864
#define WS_BYTES_PER_BUF 8192
#define GEMM_SMEM_BYTES  (WS_BYTE_BASE + 2 * WS_BYTES_PER_BUF)  // 53248

__device__ __forceinline__ void stage_chunk(
    uint32_t sb, int buf, const float* __restrict__ X,
    int R, int K, int row0, int kb, int cglob, int tid)
{
    int wq   = tid >> 5;     // 0..15
    int lane = tid & 31;
    // X chunk: 128 rows x 32 floats, 4B cp.async with zfill guards
#pragma unroll
    for (int it = 0; it < 8; it++) {
        int row = wq + 16 * it;
        int grow = row0 + row;
        int gk = kb + lane;
        int nb = (grow < R && gk < K) ? 4 : 0;
        const float* gp = X + (size_t)(grow < R ? grow : 0) * K + (gk < K ? gk : 0);
        uint32_t dst = sb + buf * XS_BYTES_PER_BUF + row * (XSF_STRIDE * 4) + lane * 4;
        asm volatile("cp.async.ca.shared.global [%0], [%1], 4, %2;"
                     :: "r"(dst), "l"(gp), "r"(nb));
    }
    // W chunk: 512 slots of 16B, permuted (see header). One per thread.
    const ull* wsrc = g_Wint + (size_t)cglob * 1024;
    {
        int kp = tid >> 5;
        int t  = tid & 31;
        int srcoff = kp * 64 + (t & 15) * 4 + (t >> 4) * 2;
        uint32_t dst = sb + WS_BYTE_BASE + buf * WS_BYTES_PER_BUF + kp * 512 + t * 16;
        asm volatile("cp.async.cg.shared.global [%0], [%1], 16;"
                     :: "r"(dst), "l"(wsrc + srcoff));
    }
}

__global__ __launch_bounds__(512, 2) void gemm_kernel(
    const float* __restrict__ Xd, const float* __restrict__ Xm)
{
    extern __shared__ __align__(16) char smem[];
    uint32_t sb = smem_u32(smem);

    const float* X;
    int R, K, nchunks, row0, zRowOffset, cbase;
    if (blockIdx.x < NB_D) {
        X = Xd; R = N_DIS; K = 383; nchunks = NCH_D;
        row0 = blockIdx.x * 128; zRowOffset = 0; cbase = 0;
    } else {
        X = Xm; R = N_MIC; K = 495; nchunks = NCH_M;
        row0 = (blockIdx.x - NB_D) * 128; zRowOffset = N_DIS; cbase = NCH_D;
    }

    int tid = threadIdx.x;
    int rg  = tid >> 4;      // 0..31: rows {rg + 32*i}
    int ft  = tid & 15;      // feature quad [4ft, 4ft+4)

    ull acc[4][4];
#pragma unroll
    for (int i = 0; i < 4; i++)
#pragma unroll
        for (int j = 0; j < 4; j++) acc[i][j] = 0ULL;

    stage_chunk(sb, 0, X, R, K, row0, 0, cbase, tid);
    asm volatile("cp.async.commit_group;" ::: "memory");

    int buf = 0;
    for (int c = 0; c < nchunks; c++) {
        if (c + 1 < nchunks) {
            stage_chunk(sb, buf ^ 1, X, R, K, row0, (c + 1) * KC, cbase + c + 1, tid);
            asm volatile("cp.async.commit_group;" ::: "memory");
            asm volatile("cp.async.wait_group 1;" ::: "memory");
        } else {
            asm volatile("cp.async.wait_group 0;" ::: "memory");
        }
        __syncthreads();

        // compute on buf: jj = one k-quad (kpairs 2jj, 2jj+1)
        const char* xb = smem + buf * XS_BYTES_PER_BUF + rg * (XSF_STRIDE * 4);
        const char* wb = smem + WS_BYTE_BASE + buf * WS_BYTES_PER_BUF + ft * 16;
#pragma unroll
        for (int jj = 0; jj < 8; jj++) {
            ulonglong2 wA0 = *(const ulonglong2*)(wb + (2 * jj) * 512);
            ulonglong2 wA1 = *(const ulonglong2*)(wb + (2 * jj) * 512 + 256);
            ulonglong2 wB0 = *(const ulonglong2*)(wb + (2 * jj + 1) * 512);
            ulonglong2 wB1 = *(const ulonglong2*)(wb + (2 * jj + 1) * 512 + 256);
#pragma unroll
            for (int i = 0; i < 4; i++) {
                ulonglong2 x2 = *(const ulonglong2*)(xb + i * (32 * XSF_STRIDE * 4) + jj * 16);
                ffma2(acc[i][0], x2.x, wA0.x);
                ffma2(acc[i][1], x2.x, wA0.y);
                ffma2(acc[i][2], x2.x, wA1.x);
                ffma2(acc[i][3], x2.x, wA1.y);
                ffma2(acc[i][0], x2.y, wB0.x);
                ffma2(acc[i][1], x2.y, wB0.y);
                ffma2(acc[i][2], x2.y, wB1.x);
                ffma2(acc[i][3], x2.y, wB1.y);
            }
        }
        __syncthreads();
        buf ^= 1;
    }

    // fold even/odd partials and write out
#pragma unroll
    for (int i = 0; i < 4; i++) {
        int grow = row0 + rg + 32 * i;
        if (grow < R) {
            float a, b;
            float4 o;
            upk2(acc[i][0], a, b); o.x = a + b;
            upk2(acc[i][1], a, b); o.y = a + b;
            upk2(acc[i][2], a, b); o.z = a + b;
            upk2(acc[i][3], a, b); o.w = a + b;
            *(float4*)(g_z + (size_t)(zRowOffset + grow) * F + 4 * ft) = o;
        }
    }
}

// ============================================================
// edge pass 1: e = leaky_relu(dot(z[src], z[dst])), atomicMax m[dst]
// ============================================================
__global__ __launch_bounds__(256) void edge_score_kernel(
    const int* __restrict__ src, const int* __restrict__ dst)
{
    int lane = threadIdx.x & 31;
    int half = lane >> 4;
    int l16  = lane & 15;
    int warp = (blockIdx.x * (blockDim.x >> 5)) + (threadIdx.x >> 5);
    int e0 = warp * 4 + half * 2;   // edges e0, e0+1

    int2 s = *(const int2*)(src + e0);
    int2 d = *(const int2*)(dst + e0);

    float4 a0 = ((const float4*)(g_z + (size_t)s.x * F))[l16];
    float4 b0 = ((const float4*)(g_z + (size_t)d.x * F))[l16];
    float4 a1 = ((const float4*)(g_z + (size_t)s.y * F))[l16];
    float4 b1 = ((const float4*)(g_z + (size_t)d.y * F))[l16];

    float p0 = a0.x * b0.x + a0.y * b0.y + a0.z * b0.z + a0.w * b0.w;
    float p1 = a1.x * b1.x + a1.y * b1.y + a1.z * b1.z + a1.w * b1.w;
#pragma unroll
    for (int off = 8; off >= 1; off >>= 1) {
        p0 += __shfl_xor_sync(0xffffffffu, p0, off);
        p1 += __shfl_xor_sync(0xffffffffu, p1, off);
    }
    if (l16 == 0) {
        float v0 = (p0 >= 0.f) ? p0 : SLOPE * p0;
        float v1 = (p1 >= 0.f) ? p1 : SLOPE * p1;
        *(float2*)(g_e + e0) = make_float2(v0, v1);
        unsigned k0 = __float_as_uint(v0); k0 = (k0 & 0x80000000u) ? ~k0 : (k0 | 0x80000000u);
        unsigned k1 = __float_as_uint(v1); k1 = (k1 & 0x80000000u) ? ~k1 : (k1 | 0x80000000u);
        atomicMax(&g_mkey[d.x], k0);
        atomicMax(&g_mkey[d.y], k1);
    }
}

// ============================================================
// edge pass 2 (fused exp + scatter, deferred normalization)
// ============================================================
__global__ __launch_bounds__(256) void edge_accum_kernel(
    const int* __restrict__ src, const int* __restrict__ dst)
{
    int lane = threadIdx.x & 31;
    int half = lane >> 4;
    int l16  = lane & 15;
    int warp = (blockIdx.x * (blockDim.x >> 5)) + (threadIdx.x >> 5);
    int e0 = warp * 4 + half * 2;

    int2 s = *(const int2*)(src + e0);
    int2 d = *(const int2*)(dst + e0);

    float4 a0 = ((const float4*)(g_z + (size_t)s.x * F))[l16];
    float4 a1 = ((const float4*)(g_z + (size_t)s.y * F))[l16];

    float ex0 = 0.f, ex1 = 0.f;
    if (l16 == 0) {
        float2 ge = *(const float2*)(g_e + e0);
        unsigned k0 = g_mkey[d.x], k1 = g_mkey[d.y];
        float m0 = __uint_as_float((k0 & 0x80000000u) ? (k0 & 0x7fffffffu) : ~k0);
        float m1 = __uint_as_float((k1 & 0x80000000u) ? (k1 & 0x7fffffffu) : ~k1);
        ex0 = expf(ge.x - m0);
        ex1 = expf(ge.y - m1);
        atomicAdd(&g_den[d.x], ex0);
        atomicAdd(&g_den[d.y], ex1);
    }
    int srcLane = half << 4;
    ex0 = __shfl_sync(0xffffffffu, ex0, srcLane);
    ex1 = __shfl_sync(0xffffffffu, ex1, srcLane);

    float* hp0 = g_h + (size_t)d.x * F + l16 * 4;
    float* hp1 = g_h + (size_t)d.y * F + l16 * 4;
    asm volatile("red.global.add.v4.f32 [%0], {%1, %2, %3, %4};"
                 :: "l"(hp0), "f"(a0.x * ex0), "f"(a0.y * ex0), "f"(a0.z * ex0), "f"(a0.w * ex0)
                 : "memory");
    asm volatile("red.global.add.v4.f32 [%0], {%1, %2, %3, %4};"
                 :: "l"(hp1), "f"(a1.x * ex1), "f"(a1.y * ex1), "f"(a1.z * ex1), "f"(a1.w * ex1)
                 : "memory");
}

// ============================================================
__global__ void rden_kernel() {
    int i = blockIdx.x * blockDim.x + threadIdx.x;
    if (i < N_NODES) {
        float d = g_den[i];
        g_den[i] = (d > 0.f) ? (1.f / d) : 0.f;
    }
}

// ============================================================
__global__ void finalize_kernel(float* __restrict__ out) {
    int i = blockIdx.x * blockDim.x + threadIdx.x;
    if (i < N_NODES * F) {
        float x = g_h[i] * g_den[i >> 6];
        out[i] = (x > 0.f) ? x : expm1f(x);
    }
}

// ============================================================
extern "C" void kernel_launch(void* const* d_in, const int* in_sizes, int n_in,
                              void* d_out, int out_size) {
    const float* d_sim  = (const float*)d_in[0];
    const float* mi_sim = (const float*)d_in[1];
    const float* W_d    = (const float*)d_in[2];
    const float* W_mi   = (const float*)d_in[3];
    const int*   src    = (const int*)d_in[4];
    const int*   dst    = (const int*)d_in[5];
    float* out = (float*)d_out;

    cudaFuncSetAttribute(gemm_kernel, cudaFuncAttributeMaxDynamicSharedMemorySize,
                         GEMM_SMEM_BYTES);

    initA_kernel<<<(N_NODES * F / 2 + 255) / 256, 256>>>();
    initB_kernel<<<(N_NODES * F / 2 + 255) / 256, 256>>>();
    prepWM_kernel<<<(N_NODES + 255) / 256, 256>>>(W_d, W_mi);

    // launch #4: the GEMM
    gemm_kernel<<<NB_D + NB_M, 512, GEMM_SMEM_BYTES>>>(d_sim, mi_sim);

    edge_score_kernel<<<N_EDGES / 32, 256>>>(src, dst);
    edge_accum_kernel<<<N_EDGES / 32, 256>>>(src, dst);
    rden_kernel<<<(N_NODES + 255) / 256, 256>>>();
    finalize_kernel<<<(N_NODES * F + 255) / 256, 256>>>(out);
}

// round 16
// speedup vs baseline: 1.0508x; 1.0508x over previous
#include <cuda_runtime.h>
#include <cstdint>

#define N_DIS   20000
#define N_MIC   80000
#define N_NODES 100000
#define N_EDGES 1600000
#define F 64
#define SLOPE 0.2f
#define KC 32

#define NB_D ((N_DIS + 127) / 128)   // 157
#define NB_M ((N_MIC + 127) / 128)   // 625
#define NCH_D ((383 + KC - 1) / KC)  // 12
#define NCH_M ((495 + KC - 1) / KC)  // 16

typedef unsigned long long ull;

// ---- scratch (static device globals: allocation-free) ----
__device__ float    g_z[(size_t)N_NODES * F];   // projected features
__device__ float    g_e[N_EDGES];               // edge scores (leaky_relu)
__device__ unsigned g_mkey[N_NODES];            // order-preserving float keys for max
__device__ float    g_den[N_NODES];             // softmax denom -> reciprocal
__device__ float    g_h[(size_t)N_NODES * F];   // accumulated (unnormalized) output
// pre-interleaved W image: per chunk, [kpair 0..15][f 0..63] ull = (W[2k][f], W[2k+1][f])
__device__ ull      g_Wint[(NCH_D + NCH_M) * 1024];

// ---- packed f32x2 helpers ----
__device__ __forceinline__ ull pk2(float a, float b) {
    ull r;
    asm("mov.b64 %0, {%1, %2};" : "=l"(r) : "f"(a), "f"(b));
    return r;
}
__device__ __forceinline__ void upk2(ull v, float& a, float& b) {
    asm("mov.b64 {%0, %1}, %2;" : "=f"(a), "=f"(b) : "l"(v));
}
__device__ __forceinline__ void ffma2(ull& d, ull a, ull b) {
    asm("fma.rn.f32x2 %0, %1, %2, %0;" : "+l"(d) : "l"(a), "l"(b));
}
__device__ __forceinline__ uint32_t smem_u32(const void* p) {
    uint32_t a;
    asm("{ .reg .u64 t; cvta.to.shared.u64 t, %1; cvt.u32.u64 %0, t; }" : "=r"(a) : "l"(p));
    return a;
}

// ============================================================
// init split so gemm_kernel is launch #4 (the profiled slot).
// ============================================================
__global__ void initA_kernel() {
    int i = blockIdx.x * blockDim.x + threadIdx.x;
    if (i < N_NODES * F / 2) g_h[i] = 0.f;
}
__global__ void initB_kernel() {
    int i = blockIdx.x * blockDim.x + threadIdx.x;
    if (i < N_NODES * F / 2) g_h[N_NODES * F / 2 + i] = 0.f;
}
__global__ void prepWM_kernel(const float* __restrict__ Wd, const float* __restrict__ Wm) {
    int i = blockIdx.x * blockDim.x + threadIdx.x;
    if (i < N_NODES) { g_mkey[i] = 0u; g_den[i] = 0.f; }
    if (i < (NCH_D + NCH_M) * 1024) {
        int c = i >> 10;
        int within = i & 1023;
        int kp = within >> 6;
        int f = within & 63;
        const float* W;
        int K, cl;
        if (c < NCH_D) { W = Wd; K = 383; cl = c; }
        else           { W = Wm; K = 495; cl = c - NCH_D; }
        int k0 = cl * KC + 2 * kp;
        float v0 = (k0     < K) ? W[(size_t)k0 * 64 + f]       : 0.f;
        float v1 = (k0 + 1 < K) ? W[(size_t)(k0 + 1) * 64 + f] : 0.f;
        g_Wint[i] = pk2(v0, v1);
    }
}

// ============================================================
// MERGED GEMM (round-12 shape: 256 thr, 8 rows x 4 feat/thread),
// k-parity FFMA2, cp.async staging, THREE-stage pipeline with a
// single __syncthreads() per chunk (stage c+2 reuses the slot of
// c-1, whose completion the iteration-c barrier already ordered).
// ============================================================
#define XSF_STRIDE       36
#define XS_BYTES_PER_BUF (128 * XSF_STRIDE * 4)          // 18432
#define WS_BYTE_BASE     (3 * XS_BYTES_PER_BUF)          // 55296
#define WS_BYTES_PER_BUF 8192
#define GEMM_SMEM_BYTES  (WS_BYTE_BASE + 3 * WS_BYTES_PER_BUF)  // 79872

__device__ __forceinline__ void stage_chunk(
    uint32_t sb, int slot, const float* __restrict__ X,
    int R, int K, int row0, int kb, int cglob, int w, int lane, int tid)
{
    // X chunk: 128 rows x 32 floats, 4B cp.async with zfill guards
#pragma unroll
    for (int it = 0; it < 16; it++) {
        int row = w + 8 * it;
        int grow = row0 + row;
        int gk = kb + lane;
        int nb = (grow < R && gk < K) ? 4 : 0;
        const float* gp = X + (size_t)(grow < R ? grow : 0) * K + (gk < K ? gk : 0);
        uint32_t dst = sb + slot * XS_BYTES_PER_BUF + row * (XSF_STRIDE * 4) + lane * 4;
        asm volatile("cp.async.ca.shared.global [%0], [%1], 4, %2;"
                     :: "r"(dst), "l"(gp), "r"(nb));
    }
    // W chunk: 1024 ull from g_Wint, 16B cp.async
    const ull* wsrc = g_Wint + (size_t)cglob * 1024;
#pragma unroll
    for (int r = 0; r < 2; r++) {
        int seg = tid + 256 * r;       // 0..511
        uint32_t dst = sb + WS_BYTE_BASE + slot * WS_BYTES_PER_BUF + seg * 16;
        asm volatile("cp.async.cg.shared.global [%0], [%1], 16;"
                     :: "r"(dst), "l"(wsrc + seg * 2));
    }
}

__global__ __launch_bounds__(256, 2) void gemm_kernel(
    const float* __restrict__ Xd, const float* __restrict__ Xm)
{
    extern __shared__ __align__(16) char smem[];
    uint32_t sb = smem_u32(smem);

    const float* X;
    int R, K, nchunks, row0, zRowOffset, cbase;
    if (blockIdx.x < NB_D) {
        X = Xd; R = N_DIS; K = 383; nchunks = NCH_D;
        row0 = blockIdx.x * 128; zRowOffset = 0; cbase = 0;
    } else {
        X = Xm; R = N_MIC; K = 495; nchunks = NCH_M;
        row0 = (blockIdx.x - NB_D) * 128; zRowOffset = N_DIS; cbase = NCH_D;
    }

    int tid  = threadIdx.x;
    int w    = tid >> 5;
    int lane = tid & 31;
    int rt   = tid >> 4;
    int ft   = tid & 15;

    ull acc[8][4];
#pragma unroll
    for (int i = 0; i < 8; i++)
#pragma unroll
        for (int j = 0; j < 4; j++) acc[i][j] = 0ULL;

    // prologue: stage chunks 0 and 1
    stage_chunk(sb, 0, X, R, K, row0, 0, cbase, w, lane, tid);
    asm volatile("cp.async.commit_group;" ::: "memory");
    if (nchunks > 1) {
        stage_chunk(sb, 1, X, R, K, row0, KC, cbase + 1, w, lane, tid);
        asm volatile("cp.async.commit_group;" ::: "memory");
    }

    for (int c = 0; c < nchunks; c++) {
        int slot = c % 3;
        // wait for chunk c's group (allow chunk c+1 in flight)
        if (c + 1 < nchunks) {
            asm volatile("cp.async.wait_group 1;" ::: "memory");
        } else {
            asm volatile("cp.async.wait_group 0;" ::: "memory");
        }
        __syncthreads();   // also orders: all warps finished compute on c-1

        // prefetch chunk c+2 into the slot freed by c-1
        if (c + 2 < nchunks) {
            stage_chunk(sb, (c + 2) % 3, X, R, K, row0, (c + 2) * KC,
                        cbase + c + 2, w, lane, tid);
            asm volatile("cp.async.commit_group;" ::: "memory");
        }

        // compute on slot
        const char* xb = smem + slot * XS_BYTES_PER_BUF + rt * (XSF_STRIDE * 4);
        const char* wb = smem + WS_BYTE_BASE + slot * WS_BYTES_PER_BUF + ft * 32;
#pragma unroll
        for (int kj = 0; kj < 16; kj++) {
            ulonglong2 w01 = *(const ulonglong2*)(wb + kj * 512);
            ulonglong2 w23 = *(const ulonglong2*)(wb + kj * 512 + 16);
#pragma unroll
            for (int i = 0; i < 8; i++) {
                ull x2 = *(const ull*)(xb + i * (16 * XSF_STRIDE * 4) + kj * 8);
                ffma2(acc[i][0], x2, w01.x);
                ffma2(acc[i][1], x2, w01.y);
                ffma2(acc[i][2], x2, w23.x);
                ffma2(acc[i][3], x2, w23.y);
            }
        }
    }

    // fold even/odd partials and write out
#pragma unroll
    for (int i = 0; i < 8; i++) {
        int grow = row0 + rt + 16 * i;
        if (grow < R) {
            float a, b;
            float4 o;
            upk2(acc[i][0], a, b); o.x = a + b;
            upk2(acc[i][1], a, b); o.y = a + b;
            upk2(acc[i][2], a, b); o.z = a + b;
            upk2(acc[i][3], a, b); o.w = a + b;
            *(float4*)(g_z + (size_t)(zRowOffset + grow) * F + 4 * ft) = o;
        }
    }
}

// ============================================================
// edge pass 1: e = leaky_relu(dot(z[src], z[dst])), atomicMax m[dst]
// ============================================================
__global__ __launch_bounds__(256) void edge_score_kernel(
    const int* __restrict__ src, const int* __restrict__ dst)
{
    int lane = threadIdx.x & 31;
    int half = lane >> 4;
    int l16  = lane & 15;
    int warp = (blockIdx.x * (blockDim.x >> 5)) + (threadIdx.x >> 5);
    int e0 = warp * 4 + half * 2;   // edges e0, e0+1

    int2 s = *(const int2*)(src + e0);
    int2 d = *(const int2*)(dst + e0);

    float4 a0 = ((const float4*)(g_z + (size_t)s.x * F))[l16];
    float4 b0 = ((const float4*)(g_z + (size_t)d.x * F))[l16];
    float4 a1 = ((const float4*)(g_z + (size_t)s.y * F))[l16];
    float4 b1 = ((const float4*)(g_z + (size_t)d.y * F))[l16];

    float p0 = a0.x * b0.x + a0.y * b0.y + a0.z * b0.z + a0.w * b0.w;
    float p1 = a1.x * b1.x + a1.y * b1.y + a1.z * b1.z + a1.w * b1.w;
#pragma unroll
    for (int off = 8; off >= 1; off >>= 1) {
        p0 += __shfl_xor_sync(0xffffffffu, p0, off);
        p1 += __shfl_xor_sync(0xffffffffu, p1, off);
    }
    if (l16 == 0) {
        float v0 = (p0 >= 0.f) ? p0 : SLOPE * p0;
        float v1 = (p1 >= 0.f) ? p1 : SLOPE * p1;
        *(float2*)(g_e + e0) = make_float2(v0, v1);
        unsigned k0 = __float_as_uint(v0); k0 = (k0 & 0x80000000u) ? ~k0 : (k0 | 0x80000000u);
        unsigned k1 = __float_as_uint(v1); k1 = (k1 & 0x80000000u) ? ~k1 : (k1 | 0x80000000u);
        atomicMax(&g_mkey[d.x], k0);
        atomicMax(&g_mkey[d.y], k1);
    }
}

// ============================================================
// edge pass 2 (fused exp + scatter, deferred normalization)
// ============================================================
__global__ __launch_bounds__(256) void edge_accum_kernel(
    const int* __restrict__ src, const int* __restrict__ dst)
{
    int lane = threadIdx.x & 31;
    int half = lane >> 4;
    int l16  = lane & 15;
    int warp = (blockIdx.x * (blockDim.x >> 5)) + (threadIdx.x >> 5);
    int e0 = warp * 4 + half * 2;

    int2 s = *(const int2*)(src + e0);
    int2 d = *(const int2*)(dst + e0);

    float4 a0 = ((const float4*)(g_z + (size_t)s.x * F))[l16];
    float4 a1 = ((const float4*)(g_z + (size_t)s.y * F))[l16];

    float ex0 = 0.f, ex1 = 0.f;
    if (l16 == 0) {
        float2 ge = *(const float2*)(g_e + e0);
        unsigned k0 = g_mkey[d.x], k1 = g_mkey[d.y];
        float m0 = __uint_as_float((k0 & 0x80000000u) ? (k0 & 0x7fffffffu) : ~k0);
        float m1 = __uint_as_float((k1 & 0x80000000u) ? (k1 & 0x7fffffffu) : ~k1);
        ex0 = expf(ge.x - m0);
        ex1 = expf(ge.y - m1);
        atomicAdd(&g_den[d.x], ex0);
        atomicAdd(&g_den[d.y], ex1);
    }
    int srcLane = half << 4;
    ex0 = __shfl_sync(0xffffffffu, ex0, srcLane);
    ex1 = __shfl_sync(0xffffffffu, ex1, srcLane);

    float* hp0 = g_h + (size_t)d.x * F + l16 * 4;
    float* hp1 = g_h + (size_t)d.y * F + l16 * 4;
    asm volatile("red.global.add.v4.f32 [%0], {%1, %2, %3, %4};"
                 :: "l"(hp0), "f"(a0.x * ex0), "f"(a0.y * ex0), "f"(a0.z * ex0), "f"(a0.w * ex0)
                 : "memory");
    asm volatile("red.global.add.v4.f32 [%0], {%1, %2, %3, %4};"
                 :: "l"(hp1), "f"(a1.x * ex1), "f"(a1.y * ex1), "f"(a1.z * ex1), "f"(a1.w * ex1)
                 : "memory");
}

// ============================================================
__global__ void rden_kernel() {
    int i = blockIdx.x * blockDim.x + threadIdx.x;
    if (i < N_NODES) {
        float d = g_den[i];
        g_den[i] = (d > 0.f) ? (1.f / d) : 0.f;
    }
}

// ============================================================
__global__ void finalize_kernel(float* __restrict__ out) {
    int i = blockIdx.x * blockDim.x + threadIdx.x;
    if (i < N_NODES * F) {
        float x = g_h[i] * g_den[i >> 6];
        out[i] = (x > 0.f) ? x : expm1f(x);
    }
}

// ============================================================
extern "C" void kernel_launch(void* const* d_in, const int* in_sizes, int n_in,
                              void* d_out, int out_size) {
    const float* d_sim  = (const float*)d_in[0];
    const float* mi_sim = (const float*)d_in[1];
    const float* W_d    = (const float*)d_in[2];
    const float* W_mi   = (const float*)d_in[3];
    const int*   src    = (const int*)d_in[4];
    const int*   dst    = (const int*)d_in[5];
    float* out = (float*)d_out;

    cudaFuncSetAttribute(gemm_kernel, cudaFuncAttributeMaxDynamicSharedMemorySize,
                         GEMM_SMEM_BYTES);

    initA_kernel<<<(N_NODES * F / 2 + 255) / 256, 256>>>();
    initB_kernel<<<(N_NODES * F / 2 + 255) / 256, 256>>>();
    prepWM_kernel<<<(N_NODES + 255) / 256, 256>>>(W_d, W_mi);

    // launch #4: the GEMM
    gemm_kernel<<<NB_D + NB_M, 256, GEMM_SMEM_BYTES>>>(d_sim, mi_sim);

    edge_score_kernel<<<N_EDGES / 32, 256>>>(src, dst);
    edge_accum_kernel<<<N_EDGES / 32, 256>>>(src, dst);
    rden_kernel<<<(N_NODES + 255) / 256, 256>>>();
    finalize_kernel<<<(N_NODES * F + 255) / 256, 256>>>(out);
}

// round 17
// speedup vs baseline: 1.2975x; 1.2348x over previous
#include <cuda_runtime.h>
#include <cstdint>

#define N_DIS   20000
#define N_MIC   80000
#define N_NODES 100000
#define N_EDGES 1600000
#define F 64
#define SLOPE 0.2f
#define KC 32

#define NB_D ((N_DIS + 127) / 128)   // 157
#define NB_M ((N_MIC + 127) / 128)   // 625
#define NCH_D ((383 + KC - 1) / KC)  // 12
#define NCH_M ((495 + KC - 1) / KC)  // 16
#define NCHT  (NCH_D + NCH_M)        // 28

typedef unsigned long long ull;

// ---- scratch (static device globals: allocation-free) ----
__device__ float    g_z[(size_t)N_NODES * F];   // projected features
__device__ float    g_e[N_EDGES];               // edge scores (leaky_relu)
__device__ unsigned g_mkey[N_NODES];            // order-preserving float keys for max
__device__ float    g_den[N_NODES];             // softmax denom -> reciprocal
__device__ float    g_h[(size_t)N_NODES * F];   // accumulated (unnormalized) output
// W fragment images (tf32 hi/lo), fragment-ordered for m16n8k8 col-B:
// index ((c*4+s)*8+nt)*32+lane ; .x = b0 (k=c*32+s*8+(lane&3), n=nt*8+(lane>>2)), .y = b1 (k+4)
__device__ float2   g_WfragHi[NCHT * 4 * 8 * 32];
__device__ float2   g_WfragLo[NCHT * 4 * 8 * 32];

__device__ __forceinline__ uint32_t smem_u32(const void* p) {
    uint32_t a;
    asm("{ .reg .u64 t; cvta.to.shared.u64 t, %1; cvt.u32.u64 %0, t; }" : "=r"(a) : "l"(p));
    return a;
}
__device__ __forceinline__ uint32_t tf32bits(float x) {
    uint32_t r;
    asm("cvt.rna.tf32.f32 %0, %1;" : "=r"(r) : "f"(x));
    return r;
}
// D += A(tf32) * B(tf32), fp32 accum, m16n8k8
__device__ __forceinline__ void mma1688(float* d, const uint32_t* a, const uint32_t* b) {
    asm("mma.sync.aligned.m16n8k8.row.col.f32.tf32.tf32.f32 "
        "{%0,%1,%2,%3},{%4,%5,%6,%7},{%8,%9},{%0,%1,%2,%3};"
        : "+f"(d[0]), "+f"(d[1]), "+f"(d[2]), "+f"(d[3])
        : "r"(a[0]), "r"(a[1]), "r"(a[2]), "r"(a[3]), "r"(b[0]), "r"(b[1]));
}

// ============================================================
// init split so gemm_kernel is launch #4 (the profiled slot).
// ============================================================
__global__ void initA_kernel() {
    int i = blockIdx.x * blockDim.x + threadIdx.x;
    if (i < N_NODES * F / 2) g_h[i] = 0.f;
}
__global__ void initB_kernel() {
    int i = blockIdx.x * blockDim.x + threadIdx.x;
    if (i < N_NODES * F / 2) g_h[N_NODES * F / 2 + i] = 0.f;
}
// zero mkey/den + build W fragment images (hi/lo tf32 split)
__global__ void prepWM_kernel(const float* __restrict__ Wd, const float* __restrict__ Wm) {
    int i = blockIdx.x * blockDim.x + threadIdx.x;
    if (i < N_NODES) { g_mkey[i] = 0u; g_den[i] = 0.f; }
    if (i < NCHT * 4 * 8 * 32) {
        int lane = i & 31;
        int nt   = (i >> 5) & 7;
        int s    = (i >> 8) & 3;
        int c    = i >> 10;
        const float* W;
        int K, cl;
        if (c < NCH_D) { W = Wd; K = 383; cl = c; }
        else           { W = Wm; K = 495; cl = c - NCH_D; }
        int k0 = cl * KC + s * 8 + (lane & 3);
        int n  = nt * 8 + (lane >> 2);
        float b0 = (k0     < K) ? W[(size_t)k0 * 64 + n]       : 0.f;
        float b1 = (k0 + 4 < K) ? W[(size_t)(k0 + 4) * 64 + n] : 0.f;
        float h0 = __uint_as_float(tf32bits(b0));
        float h1 = __uint_as_float(tf32bits(b1));
        float l0 = __uint_as_float(tf32bits(b0 - h0));
        float l1 = __uint_as_float(tf32bits(b1 - h1));
        g_WfragHi[i] = make_float2(h0, h1);
        g_WfragLo[i] = make_float2(l0, l1);
    }
}

// ============================================================
// MERGED GEMM via tf32 split mma.sync (m16n8k8):
//   Z = Xhi*Whi + Xlo*Whi + Xhi*Wlo   (fp32 accum)
// 128-row tiles, 256 threads (8 warps x 16 rows), double-buffered
// cp.async. X staged raw fp32 (stride 36 floats -> conflict-free
// A-frag LDS.32); W staged from fragment-ordered hi/lo images.
// ============================================================
#define XSF_STRIDE       36
#define XS_BYTES_PER_BUF (128 * XSF_STRIDE * 4)          // 18432
#define WS_BYTE_BASE     (2 * XS_BYTES_PER_BUF)          // 36864
#define WS_BYTES_PER_BUF 16384                            // hi 8192 + lo 8192
#define GEMM_SMEM_BYTES  (WS_BYTE_BASE + 2 * WS_BYTES_PER_BUF)  // 69632

__device__ __forceinline__ void stage_chunk(
    uint32_t sb, int buf, const float* __restrict__ X,
    int R, int K, int row0, int kb, int cglob, int w, int lane, int tid)
{
    // X chunk: 128 rows x 32 floats, 4B cp.async with zfill guards
#pragma unroll
    for (int it = 0; it < 16; it++) {
        int row = w + 8 * it;
        int grow = row0 + row;
        int gk = kb + lane;
        int nb = (grow < R && gk < K) ? 4 : 0;
        const float* gp = X + (size_t)(grow < R ? grow : 0) * K + (gk < K ? gk : 0);
        uint32_t dst = sb + buf * XS_BYTES_PER_BUF + row * (XSF_STRIDE * 4) + lane * 4;
        asm volatile("cp.async.ca.shared.global [%0], [%1], 4, %2;"
                     :: "r"(dst), "l"(gp), "r"(nb));
    }
    // W frag chunk: hi 8192B + lo 8192B, 16B cp.async (2 segs each per thread)
    const char* hsrc = (const char*)(g_WfragHi + (size_t)cglob * 1024);
    const char* lsrc = (const char*)(g_WfragLo + (size_t)cglob * 1024);
    uint32_t wbase = sb + WS_BYTE_BASE + buf * WS_BYTES_PER_BUF;
#pragma unroll
    for (int r = 0; r < 2; r++) {
        int seg = tid + 256 * r;       // 0..511 (512 x 16B = 8192B)
        asm volatile("cp.async.cg.shared.global [%0], [%1], 16;"
                     :: "r"(wbase + seg * 16), "l"(hsrc + seg * 16));
        asm volatile("cp.async.cg.shared.global [%0], [%1], 16;"
                     :: "r"(wbase + 8192 + seg * 16), "l"(lsrc + seg * 16));
    }
}

__global__ __launch_bounds__(256, 2) void gemm_kernel(
    const float* __restrict__ Xd, const float* __restrict__ Xm)
{
    extern __shared__ __align__(16) char smem[];
    uint32_t sb = smem_u32(smem);

    const float* X;
    int R, K, nchunks, row0, zRowOffset, cbase;
    if (blockIdx.x < NB_D) {
        X = Xd; R = N_DIS; K = 383; nchunks = NCH_D;
        row0 = blockIdx.x * 128; zRowOffset = 0; cbase = 0;
    } else {
        X = Xm; R = N_MIC; K = 495; nchunks = NCH_M;
        row0 = (blockIdx.x - NB_D) * 128; zRowOffset = N_DIS; cbase = NCH_D;
    }

    int tid  = threadIdx.x;
    int w    = tid >> 5;        // warp 0..7 -> rows [w*16, w*16+16)
    int lane = tid & 31;
    int g    = lane >> 2;       // 0..7
    int tg   = lane & 3;        // 0..3

    float acc[8][4];            // 8 n-tiles x 4 accum regs
#pragma unroll
    for (int nt = 0; nt < 8; nt++)
#pragma unroll
        for (int j = 0; j < 4; j++) acc[nt][j] = 0.f;

    stage_chunk(sb, 0, X, R, K, row0, 0, cbase, w, lane, tid);
    asm volatile("cp.async.commit_group;" ::: "memory");

    int buf = 0;
    for (int c = 0; c < nchunks; c++) {
        if (c + 1 < nchunks) {
            stage_chunk(sb, buf ^ 1, X, R, K, row0, (c + 1) * KC, cbase + c + 1, w, lane, tid);
            asm volatile("cp.async.commit_group;" ::: "memory");
            asm volatile("cp.async.wait_group 1;" ::: "memory");
        } else {
            asm volatile("cp.async.wait_group 0;" ::: "memory");
        }
        __syncthreads();

        const float* xw = (const float*)(smem + buf * XS_BYTES_PER_BUF) + (w * 16) * XSF_STRIDE;
        const float2* wh = (const float2*)(smem + WS_BYTE_BASE + buf * WS_BYTES_PER_BUF);
        const float2* wl = (const float2*)(smem + WS_BYTE_BASE + buf * WS_BYTES_PER_BUF + 8192);

#pragma unroll
        for (int s = 0; s < 4; s++) {
            // A fragment (raw fp32), rows g/g+8 of this warp's slice, cols s*8+tg, +4
            float ar[4];
            ar[0] = xw[(size_t)g * XSF_STRIDE + s * 8 + tg];
            ar[1] = xw[(size_t)(g + 8) * XSF_STRIDE + s * 8 + tg];
            ar[2] = xw[(size_t)g * XSF_STRIDE + s * 8 + tg + 4];
            ar[3] = xw[(size_t)(g + 8) * XSF_STRIDE + s * 8 + tg + 4];
            uint32_t ahi[4], alo[4];
#pragma unroll
            for (int q = 0; q < 4; q++) {
                ahi[q] = tf32bits(ar[q]);
                alo[q] = tf32bits(ar[q] - __uint_as_float(ahi[q]));
            }
#pragma unroll
            for (int nt = 0; nt < 8; nt++) {
                float2 bh = wh[(s * 8 + nt) * 32 + lane];
                float2 bl = wl[(s * 8 + nt) * 32 + lane];
                uint32_t bhB[2] = { __float_as_uint(bh.x), __float_as_uint(bh.y) };
                uint32_t blB[2] = { __float_as_uint(bl.x), __float_as_uint(bl.y) };
                mma1688(acc[nt], ahi, bhB);
                mma1688(acc[nt], alo, bhB);
                mma1688(acc[nt], ahi, blB);
            }
        }
        __syncthreads();
        buf ^= 1;
    }

    // epilogue: D fragment -> g_z
    int r0 = row0 + w * 16 + g;
    int r1 = r0 + 8;
#pragma unroll
    for (int nt = 0; nt < 8; nt++) {
        int col = nt * 8 + 2 * tg;
        if (r0 < R)
            *(float2*)(g_z + (size_t)(zRowOffset + r0) * F + col) = make_float2(acc[nt][0], acc[nt][1]);
        if (r1 < R)
            *(float2*)(g_z + (size_t)(zRowOffset + r1) * F + col) = make_float2(acc[nt][2], acc[nt][3]);
    }
}

// ============================================================
// edge pass 1: e = leaky_relu(dot(z[src], z[dst])), atomicMax m[dst]
// ============================================================
__global__ __launch_bounds__(256) void edge_score_kernel(
    const int* __restrict__ src, const int* __restrict__ dst)
{
    int lane = threadIdx.x & 31;
    int half = lane >> 4;
    int l16  = lane & 15;
    int warp = (blockIdx.x * (blockDim.x >> 5)) + (threadIdx.x >> 5);
    int e0 = warp * 4 + half * 2;   // edges e0, e0+1

    int2 s = *(const int2*)(src + e0);
    int2 d = *(const int2*)(dst + e0);

    float4 a0 = ((const float4*)(g_z + (size_t)s.x * F))[l16];
    float4 b0 = ((const float4*)(g_z + (size_t)d.x * F))[l16];
    float4 a1 = ((const float4*)(g_z + (size_t)s.y * F))[l16];
    float4 b1 = ((const float4*)(g_z + (size_t)d.y * F))[l16];

    float p0 = a0.x * b0.x + a0.y * b0.y + a0.z * b0.z + a0.w * b0.w;
    float p1 = a1.x * b1.x + a1.y * b1.y + a1.z * b1.z + a1.w * b1.w;
#pragma unroll
    for (int off = 8; off >= 1; off >>= 1) {
        p0 += __shfl_xor_sync(0xffffffffu, p0, off);
        p1 += __shfl_xor_sync(0xffffffffu, p1, off);
    }
    if (l16 == 0) {
        float v0 = (p0 >= 0.f) ? p0 : SLOPE * p0;
        float v1 = (p1 >= 0.f) ? p1 : SLOPE * p1;
        *(float2*)(g_e + e0) = make_float2(v0, v1);
        unsigned k0 = __float_as_uint(v0); k0 = (k0 & 0x80000000u) ? ~k0 : (k0 | 0x80000000u);
        unsigned k1 = __float_as_uint(v1); k1 = (k1 & 0x80000000u) ? ~k1 : (k1 | 0x80000000u);
        atomicMax(&g_mkey[d.x], k0);
        atomicMax(&g_mkey[d.y], k1);
    }
}

// ============================================================
// edge pass 2 (fused exp + scatter, deferred normalization)
// ============================================================
__global__ __launch_bounds__(256) void edge_accum_kernel(
    const int* __restrict__ src, const int* __restrict__ dst)
{
    int lane = threadIdx.x & 31;
    int half = lane >> 4;
    int l16  = lane & 15;
    int warp = (blockIdx.x * (blockDim.x >> 5)) + (threadIdx.x >> 5);
    int e0 = warp * 4 + half * 2;

    int2 s = *(const int2*)(src + e0);
    int2 d = *(const int2*)(dst + e0);

    float4 a0 = ((const float4*)(g_z + (size_t)s.x * F))[l16];
    float4 a1 = ((const float4*)(g_z + (size_t)s.y * F))[l16];

    float ex0 = 0.f, ex1 = 0.f;
    if (l16 == 0) {
        float2 ge = *(const float2*)(g_e + e0);
        unsigned k0 = g_mkey[d.x], k1 = g_mkey[d.y];
        float m0 = __uint_as_float((k0 & 0x80000000u) ? (k0 & 0x7fffffffu) : ~k0);
        float m1 = __uint_as_float((k1 & 0x80000000u) ? (k1 & 0x7fffffffu) : ~k1);
        ex0 = expf(ge.x - m0);
        ex1 = expf(ge.y - m1);
        atomicAdd(&g_den[d.x], ex0);
        atomicAdd(&g_den[d.y], ex1);
    }
    int srcLane = half << 4;
    ex0 = __shfl_sync(0xffffffffu, ex0, srcLane);
    ex1 = __shfl_sync(0xffffffffu, ex1, srcLane);

    float* hp0 = g_h + (size_t)d.x * F + l16 * 4;
    float* hp1 = g_h + (size_t)d.y * F + l16 * 4;
    asm volatile("red.global.add.v4.f32 [%0], {%1, %2, %3, %4};"
                 :: "l"(hp0), "f"(a0.x * ex0), "f"(a0.y * ex0), "f"(a0.z * ex0), "f"(a0.w * ex0)
                 : "memory");
    asm volatile("red.global.add.v4.f32 [%0], {%1, %2, %3, %4};"
                 :: "l"(hp1), "f"(a1.x * ex1), "f"(a1.y * ex1), "f"(a1.z * ex1), "f"(a1.w * ex1)
                 : "memory");
}

// ============================================================
__global__ void rden_kernel() {
    int i = blockIdx.x * blockDim.x + threadIdx.x;
    if (i < N_NODES) {
        float d = g_den[i];
        g_den[i] = (d > 0.f) ? (1.f / d) : 0.f;
    }
}

// ============================================================
__global__ void finalize_kernel(float* __restrict__ out) {
    int i = blockIdx.x * blockDim.x + threadIdx.x;
    if (i < N_NODES * F) {
        float x = g_h[i] * g_den[i >> 6];
        out[i] = (x > 0.f) ? x : expm1f(x);
    }
}

// ============================================================
extern "C" void kernel_launch(void* const* d_in, const int* in_sizes, int n_in,
                              void* d_out, int out_size) {
    const float* d_sim  = (const float*)d_in[0];
    const float* mi_sim = (const float*)d_in[1];
    const float* W_d    = (const float*)d_in[2];
    const float* W_mi   = (const float*)d_in[3];
    const int*   src    = (const int*)d_in[4];
    const int*   dst    = (const int*)d_in[5];
    float* out = (float*)d_out;

    cudaFuncSetAttribute(gemm_kernel, cudaFuncAttributeMaxDynamicSharedMemorySize,
                         GEMM_SMEM_BYTES);

    initA_kernel<<<(N_NODES * F / 2 + 255) / 256, 256>>>();
    initB_kernel<<<(N_NODES * F / 2 + 255) / 256, 256>>>();
    prepWM_kernel<<<(N_NODES + 255) / 256, 256>>>(W_d, W_mi);

    // launch #4: the GEMM
    gemm_kernel<<<NB_D + NB_M, 256, GEMM_SMEM_BYTES>>>(d_sim, mi_sim);

    edge_score_kernel<<<N_EDGES / 32, 256>>>(src, dst);
    edge_accum_kernel<<<N_EDGES / 32, 256>>>(src, dst);
    rden_kernel<<<(N_NODES + 255) / 256, 256>>>();
    finalize_kernel<<<(N_NODES * F + 255) / 256, 256>>>(out);
}